// round 9
// baseline (speedup 1.0000x reference)
#include <cuda_runtime.h>
#include <cuda_fp16.h>
#include <math.h>
#include <stdint.h>

#define B_DIM   8
#define HW_DIM  3136
#define C_DIM   256
#define NROWS   (B_DIM * HW_DIM)        // 25088
#define PITCH   68                      // transform kernel smem pitch
#define JT      64                      // j tile
#define NJT     (HW_DIM / JT)           // 49

// fused-kernel smem (bytes). Pitches in uint4 units: X rows 36 (=4 mod 8),
// T/S rows 12 (=4 mod 8) -> conflict-free LDS.128 fragment gathers.
// T tile holds HALF the c-range (128 rows) and is reloaded twice per j-iter,
// keeping the CTA footprint <= 108KB so 2 CTAs co-reside per SM.
#define XP      36                      // X row pitch (uint4); row = 256 halves = 32 u4
#define TP      12                      // T/S row pitch (uint4); row = 64 halves = 8 u4
#define SM_XI   0
#define SM_XJ   36864                   // 64*36*16
#define SM_TT   73728                   // 128*12*16 = 24576 (half-c T tile)
#define SM_SS   98304                   // 64*12*16  = 12288
#define SM_TOT  110592

// device-global scratch, fp16 (pre-rounded once by producers)
__device__ __align__(16) unsigned short g_xn[(size_t)NROWS * C_DIM];          // [row][c]
__device__ __align__(16) unsigned short g_tt[(size_t)B_DIM * C_DIM * HW_DIM]; // [b][c][hw]

__device__ __forceinline__ uint32_t h2pack(float a, float b) {
    __half2 h = __floats2half2_rn(a, b);
    return *reinterpret_cast<uint32_t*>(&h);
}
__device__ __forceinline__ uint32_t smem_u32(const void* p) {
    uint32_t a;
    asm("{ .reg .u64 t; cvta.to.shared.u64 t, %1; cvt.u32.u64 %0, t; }" : "=r"(a) : "l"(p));
    return a;
}
__device__ __forceinline__ void cp16(uint32_t dst, const void* src) {
    asm volatile("{ .reg .u64 g; cvta.to.global.u64 g, %1;"
                 " cp.async.cg.shared.global [%0], [g], 16; }" :: "r"(dst), "l"(src));
}
#define CP_COMMIT() asm volatile("cp.async.commit_group;" ::: "memory")
#define CP_WAIT0()  asm volatile("cp.async.wait_group 0;" ::: "memory")

// fp16 mma, fp32 accum
__device__ __forceinline__ void mma16(float* d, uint32_t a0, uint32_t a1,
                                      uint32_t a2, uint32_t a3,
                                      uint32_t b0, uint32_t b1) {
    asm volatile(
        "mma.sync.aligned.m16n8k16.row.col.f32.f16.f16.f32 "
        "{%0,%1,%2,%3}, {%4,%5,%6,%7}, {%8,%9}, {%0,%1,%2,%3};"
        : "+f"(d[0]), "+f"(d[1]), "+f"(d[2]), "+f"(d[3])
        : "r"(a0), "r"(a1), "r"(a2), "r"(a3), "r"(b0), "r"(b1));
}

// ---------------------------------------------------------------------------
// Kernel A: L2 normalize -> g_xn (fp16)
// ---------------------------------------------------------------------------
__global__ void norm_kernel(const float* __restrict__ x) {
    int row  = blockIdx.x * 8 + threadIdx.y;
    int lane = threadIdx.x;
    const float4* xr = reinterpret_cast<const float4*>(x) + (size_t)row * (C_DIM / 4);
    float4 v0 = xr[lane];
    float4 v1 = xr[lane + 32];
    float s = v0.x*v0.x + v0.y*v0.y + v0.z*v0.z + v0.w*v0.w
            + v1.x*v1.x + v1.y*v1.y + v1.z*v1.z + v1.w*v1.w;
#pragma unroll
    for (int off = 16; off > 0; off >>= 1) s += __shfl_xor_sync(0xffffffffu, s, off);
    float inv = rsqrtf(fmaxf(s, 1e-12f));
    uint2 o0 = make_uint2(h2pack(v0.x*inv, v0.y*inv), h2pack(v0.z*inv, v0.w*inv));
    uint2 o1 = make_uint2(h2pack(v1.x*inv, v1.y*inv), h2pack(v1.z*inv, v1.w*inv));
    uint2* o = reinterpret_cast<uint2*>(g_xn) + (size_t)row * (C_DIM / 4);
    o[lane] = o0; o[lane + 32] = o1;
}

// ---------------------------------------------------------------------------
// Kernel B: t = x @ W (fp32 exact), stored transposed fp16: g_tt[b][c][hw].
// Output tile staged in smem so global stores are coalesced 16B chunks.
// ---------------------------------------------------------------------------
__global__ __launch_bounds__(256)
void transform_kernel(const float* __restrict__ x, const float* __restrict__ W) {
    __shared__ float sXT[64 * PITCH];
    __shared__ float sWS[64 * PITCH];
    __shared__ uint32_t sTO[64 * 36];      // [c][hw-pair] staging, pitch 36 u32
    int row0 = blockIdx.x * 64, c0 = blockIdx.y * 64;
    int tid = threadIdx.x, tx = tid & 15, ty = tid >> 4;
    float acc[4][4] = {};
    for (int k0 = 0; k0 < C_DIM; k0 += 64) {
        __syncthreads();
#pragma unroll
        for (int q = 0; q < 16; q++) {
            int idx = tid + q * 256, a = idx >> 6, bc = idx & 63;
            sXT[bc * PITCH + a] = x[(size_t)(row0 + a) * C_DIM + k0 + bc];
            sWS[a * PITCH + bc] = W[(size_t)(k0 + a) * C_DIM + c0 + bc];
        }
        __syncthreads();
#pragma unroll 8
        for (int kk = 0; kk < 64; kk++) {
            float4 av = *reinterpret_cast<const float4*>(&sXT[kk * PITCH + 4 * ty]);
            float4 bv = *reinterpret_cast<const float4*>(&sWS[kk * PITCH + 4 * tx]);
            float aq[4] = {av.x, av.y, av.z, av.w};
            float br[4] = {bv.x, bv.y, bv.z, bv.w};
#pragma unroll
            for (int q = 0; q < 4; q++)
#pragma unroll
                for (int r = 0; r < 4; r++) acc[q][r] += aq[q] * br[r];
        }
    }
    // transpose through smem: sTO[c][hw/2]
#pragma unroll
    for (int r = 0; r < 4; r++)
#pragma unroll
        for (int qp = 0; qp < 2; qp++)
            sTO[(4 * tx + r) * 36 + 2 * ty + qp] =
                h2pack(acc[2 * qp][r], acc[2 * qp + 1][r]);
    __syncthreads();
    // coalesced 16B writes along hw
    int bb = row0 / HW_DIM, hw0 = row0 - bb * HW_DIM;
    int c = tid >> 2, ch = tid & 3;
    uint4 v = *reinterpret_cast<const uint4*>(&sTO[c * 36 + ch * 8]);
    *reinterpret_cast<uint4*>(
        &g_tt[((size_t)bb * C_DIM + c0 + c) * HW_DIM + hw0 + ch * 16]) = v;
    uint4 v2 = *reinterpret_cast<const uint4*>(&sTO[c * 36 + ch * 8 + 4]);
    *reinterpret_cast<uint4*>(
        &g_tt[((size_t)bb * C_DIM + c0 + c) * HW_DIM + hw0 + ch * 16 + 8]) = v2;
}

// ---------------------------------------------------------------------------
// Kernel C: fused pass, mma.sync fp16, 2 CTAs/SM.
//   per 64-j tile: ph1 S = Xi@Xj^T; relu^2 -> sS; ph2 in two c-halves with the
//   half-T buffer reloaded mid-iteration (latency covered by co-resident CTA).
// ---------------------------------------------------------------------------
__global__ __launch_bounds__(256, 2)
void ppm_fused(float* __restrict__ y) {
    extern __shared__ char smem[];
    uint32_t sbase = smem_u32(smem);
    const uint4* Xi4 = reinterpret_cast<const uint4*>(smem + SM_XI);
    const uint4* Xj4 = reinterpret_cast<const uint4*>(smem + SM_XJ);
    const uint4* T4  = reinterpret_cast<const uint4*>(smem + SM_TT);
    uint32_t*    sS  = reinterpret_cast<uint32_t*>(smem + SM_SS);
    const uint4* S4  = reinterpret_cast<const uint4*>(smem + SM_SS);

    int b  = blockIdx.y;
    int i0 = blockIdx.x * JT;
    const unsigned short* Xg = g_xn + (size_t)b * HW_DIM * C_DIM;
    const unsigned short* Tg = g_tt + (size_t)b * C_DIM * HW_DIM;

    int tid = threadIdx.x, w = tid >> 5, lane = tid & 31;
    int gid = lane >> 2, tig = lane & 3;
    int wr = w & 1, wn = w >> 1;

    auto loadX = [&](int r0, uint32_t dstb) {
#pragma unroll
        for (int q = 0; q < 8; q++) {
            int idx = tid + q * 256, r = idx >> 5, c4 = idx & 31;
            cp16(sbase + dstb + (uint32_t)(r * XP + c4) * 16,
                 Xg + (size_t)(r0 + r) * C_DIM + c4 * 8);
        }
    };
    // half-c T tile: rows c_half = 0..127 for global c = 128*h + c_half
    auto loadT = [&](int j0, int h) {
#pragma unroll
        for (int q = 0; q < 4; q++) {
            int idx = tid + q * 256, c = idx >> 3, k4 = idx & 7;
            cp16(sbase + SM_TT + (uint32_t)(c * TP + k4) * 16,
                 Tg + (size_t)(128 * h + c) * HW_DIM + j0 + k4 * 8);
        }
    };

    loadX(i0, SM_XI);
    loadX(0, SM_XJ);
    loadT(0, 0);
    CP_COMMIT();

    float yacc[2][8][4];
#pragma unroll
    for (int mb = 0; mb < 2; mb++)
#pragma unroll
        for (int nt = 0; nt < 8; nt++)
#pragma unroll
            for (int q = 0; q < 4; q++) yacc[mb][nt][q] = 0.f;

    for (int j = 0; j < NJT; j++) {
        CP_WAIT0();                    // Xj(j) + T-half0(j) ready
        __syncthreads();

        // ---- phase 1: S(32x16/warp) = Xi @ Xj^T over K=256
        float sacc[2][2][4] = {};
#pragma unroll
        for (int kc = 0; kc < 8; kc++) {
            uint4 Ag[2], Ag8[2];
#pragma unroll
            for (int mb = 0; mb < 2; mb++) {
                int r1 = 32 * wr + 16 * mb + gid;
                Ag[mb]  = Xi4[r1 * XP + 4 * kc + tig];
                Ag8[mb] = Xi4[(r1 + 8) * XP + 4 * kc + tig];
            }
            uint4 Bn[2];
#pragma unroll
            for (int nb = 0; nb < 2; nb++) {
                int n1 = 16 * wn + 8 * nb + gid;
                Bn[nb] = Xj4[n1 * XP + 4 * kc + tig];
            }
#pragma unroll
            for (int s = 0; s < 2; s++)
#pragma unroll
                for (int mb = 0; mb < 2; mb++) {
                    const uint32_t* ag  = reinterpret_cast<const uint32_t*>(&Ag[mb]);
                    const uint32_t* ag8 = reinterpret_cast<const uint32_t*>(&Ag8[mb]);
#pragma unroll
                    for (int nb = 0; nb < 2; nb++) {
                        const uint32_t* bn = reinterpret_cast<const uint32_t*>(&Bn[nb]);
                        mma16(sacc[mb][nb], ag[2*s], ag8[2*s], ag[2*s+1], ag8[2*s+1],
                              bn[2*s], bn[2*s+1]);
                    }
                }
        }
        // relu^2 -> sS
#pragma unroll
        for (int mb = 0; mb < 2; mb++)
#pragma unroll
            for (int nb = 0; nb < 2; nb++) {
                int r1 = 32 * wr + 16 * mb + gid;
                int cw = 8 * wn + 4 * nb + tig;
                float v0 = fmaxf(sacc[mb][nb][0], 0.f), v1 = fmaxf(sacc[mb][nb][1], 0.f);
                float v2 = fmaxf(sacc[mb][nb][2], 0.f), v3 = fmaxf(sacc[mb][nb][3], 0.f);
                sS[r1 * (TP * 4) + cw]       = h2pack(v0 * v0, v1 * v1);
                sS[(r1 + 8) * (TP * 4) + cw] = h2pack(v2 * v2, v3 * v3);
            }
        __syncthreads();               // sS valid; sXj free

        if (j + 1 < NJT) { loadX((j + 1) * JT, SM_XJ); CP_COMMIT(); }

        // ---- phase 2, both c-halves (warp tile 32x32 per half)
#pragma unroll
        for (int h = 0; h < 2; h++) {
#pragma unroll
            for (int kc = 0; kc < 2; kc++) {
                uint4 Ag[2], Ag8[2];
#pragma unroll
                for (int mb = 0; mb < 2; mb++) {
                    int r1 = 32 * wr + 16 * mb + gid;
                    Ag[mb]  = S4[r1 * TP + 4 * kc + tig];
                    Ag8[mb] = S4[(r1 + 8) * TP + 4 * kc + tig];
                }
#pragma unroll
                for (int nt = 0; nt < 4; nt++) {
                    int c = 32 * wn + 8 * nt + gid;          // c within half
                    uint4 Bv = T4[c * TP + 4 * kc + tig];
                    const uint32_t* bn = reinterpret_cast<const uint32_t*>(&Bv);
#pragma unroll
                    for (int s = 0; s < 2; s++)
#pragma unroll
                        for (int mb = 0; mb < 2; mb++) {
                            const uint32_t* ag  = reinterpret_cast<const uint32_t*>(&Ag[mb]);
                            const uint32_t* ag8 = reinterpret_cast<const uint32_t*>(&Ag8[mb]);
                            mma16(yacc[mb][4 * h + nt], ag[2*s], ag8[2*s],
                                  ag[2*s+1], ag8[2*s+1], bn[2*s], bn[2*s+1]);
                        }
                }
            }
            if (h == 0) {
                __syncthreads();                       // half-0 reads done
                loadT(j * JT, 1); CP_COMMIT();         // fetch half-1 (same buf)
                CP_WAIT0();                            // also retires Xj(j+1)
                __syncthreads();
            }
        }
        __syncthreads();                               // half-1 reads done
        if (j + 1 < NJT) { loadT((j + 1) * JT, 0); CP_COMMIT(); }
    }

    // epilogue: c = 128*(nt2>>2) + 32*wn + 8*(nt2&3) + 2*tig
    float* Yb = y + ((size_t)b * HW_DIM + i0) * C_DIM;
#pragma unroll
    for (int mb = 0; mb < 2; mb++) {
        int r1 = 32 * wr + 16 * mb + gid;
#pragma unroll
        for (int nt2 = 0; nt2 < 8; nt2++) {
            int c = 128 * (nt2 >> 2) + 32 * wn + 8 * (nt2 & 3) + 2 * tig;
            *reinterpret_cast<float2*>(&Yb[(size_t)r1 * C_DIM + c]) =
                make_float2(yacc[mb][nt2][0], yacc[mb][nt2][1]);
            *reinterpret_cast<float2*>(&Yb[(size_t)(r1 + 8) * C_DIM + c]) =
                make_float2(yacc[mb][nt2][2], yacc[mb][nt2][3]);
        }
    }
}

// ---------------------------------------------------------------------------
extern "C" void kernel_launch(void* const* d_in, const int* in_sizes, int n_in,
                              void* d_out, int out_size) {
    const float* x = (const float*)d_in[0];
    const float* W = (const float*)d_in[1];
    float* y = (float*)d_out;
    (void)in_sizes; (void)n_in; (void)out_size;

    norm_kernel<<<NROWS / 8, dim3(32, 8)>>>(x);
    transform_kernel<<<dim3(NROWS / 64, C_DIM / 64), 256>>>(x, W);

    cudaFuncSetAttribute(ppm_fused, cudaFuncAttributeMaxDynamicSharedMemorySize, SM_TOT);
    ppm_fused<<<dim3(HW_DIM / JT, B_DIM), 256, SM_TOT>>>(y);
}

// round 10
// speedup vs baseline: 1.0495x; 1.0495x over previous
#include <cuda_runtime.h>
#include <cuda_fp16.h>
#include <math.h>
#include <stdint.h>

#define B_DIM   8
#define HW_DIM  3136
#define C_DIM   256
#define NROWS   (B_DIM * HW_DIM)        // 25088
#define PITCH   68                      // transform kernel smem pitch
#define JT      64                      // j tile
#define NJT     (HW_DIM / JT)           // 49

// smem (bytes). X rows pitch 36 u4, T/S rows pitch 12 u4 (both =4 mod 8 ->
// conflict-free LDS.128 fragment gathers). Xj and T double-buffered.
#define XP      36
#define TP      12
#define SM_XI   0                       // 64*36*16  = 36864
#define SM_XJ0  36864                   // 36864
#define SM_XJ1  73728                   // 36864
#define SM_TT0  110592                  // 256*12*16 = 49152
#define SM_TT1  159744                  // 49152
#define SM_SS   208896                  // 64*12*16  = 12288
#define SM_TOT  221184

// device-global scratch, fp16 (pre-rounded once by producers)
__device__ __align__(16) unsigned short g_xn[(size_t)NROWS * C_DIM];          // [row][c]
__device__ __align__(16) unsigned short g_tt[(size_t)B_DIM * C_DIM * HW_DIM]; // [b][c][hw]

__device__ __forceinline__ uint32_t h2pack(float a, float b) {
    __half2 h = __floats2half2_rn(a, b);
    return *reinterpret_cast<uint32_t*>(&h);
}
__device__ __forceinline__ uint32_t smem_u32(const void* p) {
    uint32_t a;
    asm("{ .reg .u64 t; cvta.to.shared.u64 t, %1; cvt.u32.u64 %0, t; }" : "=r"(a) : "l"(p));
    return a;
}
__device__ __forceinline__ void cp16(uint32_t dst, const void* src) {
    asm volatile("{ .reg .u64 g; cvta.to.global.u64 g, %1;"
                 " cp.async.cg.shared.global [%0], [g], 16; }" :: "r"(dst), "l"(src));
}
#define CP_COMMIT() asm volatile("cp.async.commit_group;" ::: "memory")
#define CP_WAIT0()  asm volatile("cp.async.wait_group 0;" ::: "memory")
#define CP_WAIT1()  asm volatile("cp.async.wait_group 1;" ::: "memory")

// fp16 mma, fp32 accum
__device__ __forceinline__ void mma16(float* d, uint32_t a0, uint32_t a1,
                                      uint32_t a2, uint32_t a3,
                                      uint32_t b0, uint32_t b1) {
    asm volatile(
        "mma.sync.aligned.m16n8k16.row.col.f32.f16.f16.f32 "
        "{%0,%1,%2,%3}, {%4,%5,%6,%7}, {%8,%9}, {%0,%1,%2,%3};"
        : "+f"(d[0]), "+f"(d[1]), "+f"(d[2]), "+f"(d[3])
        : "r"(a0), "r"(a1), "r"(a2), "r"(a3), "r"(b0), "r"(b1));
}

// ---------------------------------------------------------------------------
// Kernel A: L2 normalize -> g_xn (fp16)
// ---------------------------------------------------------------------------
__global__ void norm_kernel(const float* __restrict__ x) {
    int row  = blockIdx.x * 8 + threadIdx.y;
    int lane = threadIdx.x;
    const float4* xr = reinterpret_cast<const float4*>(x) + (size_t)row * (C_DIM / 4);
    float4 v0 = xr[lane];
    float4 v1 = xr[lane + 32];
    float s = v0.x*v0.x + v0.y*v0.y + v0.z*v0.z + v0.w*v0.w
            + v1.x*v1.x + v1.y*v1.y + v1.z*v1.z + v1.w*v1.w;
#pragma unroll
    for (int off = 16; off > 0; off >>= 1) s += __shfl_xor_sync(0xffffffffu, s, off);
    float inv = rsqrtf(fmaxf(s, 1e-12f));
    uint2 o0 = make_uint2(h2pack(v0.x*inv, v0.y*inv), h2pack(v0.z*inv, v0.w*inv));
    uint2 o1 = make_uint2(h2pack(v1.x*inv, v1.y*inv), h2pack(v1.z*inv, v1.w*inv));
    uint2* o = reinterpret_cast<uint2*>(g_xn) + (size_t)row * (C_DIM / 4);
    o[lane] = o0; o[lane + 32] = o1;
}

// ---------------------------------------------------------------------------
// Kernel B: t = x @ W (fp32 exact), stored transposed fp16: g_tt[b][c][hw].
// Output tile staged in smem -> coalesced 16B global stores.
// ---------------------------------------------------------------------------
__global__ __launch_bounds__(256)
void transform_kernel(const float* __restrict__ x, const float* __restrict__ W) {
    __shared__ float sXT[64 * PITCH];
    __shared__ float sWS[64 * PITCH];
    __shared__ uint32_t sTO[64 * 36];
    int row0 = blockIdx.x * 64, c0 = blockIdx.y * 64;
    int tid = threadIdx.x, tx = tid & 15, ty = tid >> 4;
    float acc[4][4] = {};
    for (int k0 = 0; k0 < C_DIM; k0 += 64) {
        __syncthreads();
#pragma unroll
        for (int q = 0; q < 16; q++) {
            int idx = tid + q * 256, a = idx >> 6, bc = idx & 63;
            sXT[bc * PITCH + a] = x[(size_t)(row0 + a) * C_DIM + k0 + bc];
            sWS[a * PITCH + bc] = W[(size_t)(k0 + a) * C_DIM + c0 + bc];
        }
        __syncthreads();
#pragma unroll 8
        for (int kk = 0; kk < 64; kk++) {
            float4 av = *reinterpret_cast<const float4*>(&sXT[kk * PITCH + 4 * ty]);
            float4 bv = *reinterpret_cast<const float4*>(&sWS[kk * PITCH + 4 * tx]);
            float aq[4] = {av.x, av.y, av.z, av.w};
            float br[4] = {bv.x, bv.y, bv.z, bv.w};
#pragma unroll
            for (int q = 0; q < 4; q++)
#pragma unroll
                for (int r = 0; r < 4; r++) acc[q][r] += aq[q] * br[r];
        }
    }
#pragma unroll
    for (int r = 0; r < 4; r++)
#pragma unroll
        for (int qp = 0; qp < 2; qp++)
            sTO[(4 * tx + r) * 36 + 2 * ty + qp] =
                h2pack(acc[2 * qp][r], acc[2 * qp + 1][r]);
    __syncthreads();
    int bb = row0 / HW_DIM, hw0 = row0 - bb * HW_DIM;
    int c = tid >> 2, ch = tid & 3;
    uint4 v = *reinterpret_cast<const uint4*>(&sTO[c * 36 + ch * 8]);
    *reinterpret_cast<uint4*>(
        &g_tt[((size_t)bb * C_DIM + c0 + c) * HW_DIM + hw0 + ch * 16]) = v;
    uint4 v2 = *reinterpret_cast<const uint4*>(&sTO[c * 36 + ch * 8 + 4]);
    *reinterpret_cast<uint4*>(
        &g_tt[((size_t)bb * C_DIM + c0 + c) * HW_DIM + hw0 + ch * 16 + 8]) = v2;
}

// ---------------------------------------------------------------------------
// Kernel C: fused pass, mma.sync fp16, fully double-buffered pipeline.
//   Loads for iteration j+2 are issued inside iteration j, so the top-of-loop
//   wait never stalls. 3 barriers/iter, no exposed cp.async latency.
// ---------------------------------------------------------------------------
__global__ __launch_bounds__(256)
void ppm_fused(float* __restrict__ y) {
    extern __shared__ char smem[];
    uint32_t sbase = smem_u32(smem);
    const uint4* Xi4 = reinterpret_cast<const uint4*>(smem + SM_XI);
    uint32_t*    sS  = reinterpret_cast<uint32_t*>(smem + SM_SS);
    const uint4* S4  = reinterpret_cast<const uint4*>(smem + SM_SS);

    int b  = blockIdx.y;
    int i0 = blockIdx.x * JT;
    const unsigned short* Xg = g_xn + (size_t)b * HW_DIM * C_DIM;
    const unsigned short* Tg = g_tt + (size_t)b * C_DIM * HW_DIM;

    int tid = threadIdx.x, w = tid >> 5, lane = tid & 31;
    int gid = lane >> 2, tig = lane & 3;
    int wr = w & 1, wn = w >> 1;

    const uint32_t xjOff[2] = {SM_XJ0, SM_XJ1};
    const uint32_t ttOff[2] = {SM_TT0, SM_TT1};

    auto loadX = [&](int r0, uint32_t dstb) {
#pragma unroll
        for (int q = 0; q < 8; q++) {
            int idx = tid + q * 256, r = idx >> 5, c4 = idx & 31;
            cp16(sbase + dstb + (uint32_t)(r * XP + c4) * 16,
                 Xg + (size_t)(r0 + r) * C_DIM + c4 * 8);
        }
    };
    auto loadT = [&](int j0, uint32_t dstb) {
#pragma unroll
        for (int q = 0; q < 8; q++) {
            int idx = tid + q * 256, c = idx >> 3, k4 = idx & 7;
            cp16(sbase + dstb + (uint32_t)(c * TP + k4) * 16,
                 Tg + (size_t)c * HW_DIM + j0 + k4 * 8);
        }
    };

    // prologue: group0 = {Xi, Xj(0), T(0)}, group1 = {Xj(1), T(1)}
    loadX(i0, SM_XI);
    loadX(0, SM_XJ0);
    loadT(0, SM_TT0);
    CP_COMMIT();
    loadX(JT, SM_XJ1);
    loadT(JT, SM_TT1);
    CP_COMMIT();

    float yacc[2][8][4];
#pragma unroll
    for (int mb = 0; mb < 2; mb++)
#pragma unroll
        for (int nt = 0; nt < 8; nt++)
#pragma unroll
            for (int q = 0; q < 4; q++) yacc[mb][nt][q] = 0.f;

    for (int j = 0; j < NJT; j++) {
        int s = j & 1;
        if (j == NJT - 1) CP_WAIT0(); else CP_WAIT1();   // group j done (landed an iter ago)
        __syncthreads();
        const uint4* Xj4 = reinterpret_cast<const uint4*>(smem + xjOff[s]);
        const uint4* T4  = reinterpret_cast<const uint4*>(smem + ttOff[s]);

        // ---- phase 1: S(32x16/warp) = Xi @ Xj^T over K=256
        float sacc[2][2][4] = {};
#pragma unroll
        for (int kc = 0; kc < 8; kc++) {
            uint4 Ag[2], Ag8[2];
#pragma unroll
            for (int mb = 0; mb < 2; mb++) {
                int r1 = 32 * wr + 16 * mb + gid;
                Ag[mb]  = Xi4[r1 * XP + 4 * kc + tig];
                Ag8[mb] = Xi4[(r1 + 8) * XP + 4 * kc + tig];
            }
            uint4 Bn[2];
#pragma unroll
            for (int nb = 0; nb < 2; nb++) {
                int n1 = 16 * wn + 8 * nb + gid;
                Bn[nb] = Xj4[n1 * XP + 4 * kc + tig];
            }
#pragma unroll
            for (int ss = 0; ss < 2; ss++)
#pragma unroll
                for (int mb = 0; mb < 2; mb++) {
                    const uint32_t* ag  = reinterpret_cast<const uint32_t*>(&Ag[mb]);
                    const uint32_t* ag8 = reinterpret_cast<const uint32_t*>(&Ag8[mb]);
#pragma unroll
                    for (int nb = 0; nb < 2; nb++) {
                        const uint32_t* bn = reinterpret_cast<const uint32_t*>(&Bn[nb]);
                        mma16(sacc[mb][nb], ag[2*ss], ag8[2*ss], ag[2*ss+1], ag8[2*ss+1],
                              bn[2*ss], bn[2*ss+1]);
                    }
                }
        }
        // relu^2 -> sS
#pragma unroll
        for (int mb = 0; mb < 2; mb++)
#pragma unroll
            for (int nb = 0; nb < 2; nb++) {
                int r1 = 32 * wr + 16 * mb + gid;
                int cw = 8 * wn + 4 * nb + tig;
                float v0 = fmaxf(sacc[mb][nb][0], 0.f), v1 = fmaxf(sacc[mb][nb][1], 0.f);
                float v2 = fmaxf(sacc[mb][nb][2], 0.f), v3 = fmaxf(sacc[mb][nb][3], 0.f);
                sS[r1 * (TP * 4) + cw]       = h2pack(v0 * v0, v1 * v1);
                sS[(r1 + 8) * (TP * 4) + cw] = h2pack(v2 * v2, v3 * v3);
            }
        __syncthreads();               // sS visible; all ph1 reads of Xj[s] done

        // overlap: refill Xj[s] for iteration j+2 while ph2 runs
        if (j + 2 < NJT) loadX((j + 2) * JT, xjOff[s]);

        // ---- phase 2: Y(32x64/warp) += S @ T over K=64
#pragma unroll
        for (int kc = 0; kc < 2; kc++) {
            uint4 Ag[2], Ag8[2];
#pragma unroll
            for (int mb = 0; mb < 2; mb++) {
                int r1 = 32 * wr + 16 * mb + gid;
                Ag[mb]  = S4[r1 * TP + 4 * kc + tig];
                Ag8[mb] = S4[(r1 + 8) * TP + 4 * kc + tig];
            }
#pragma unroll
            for (int nt = 0; nt < 8; nt++) {
                int c = 64 * wn + 8 * nt + gid;
                uint4 Bv = T4[c * TP + 4 * kc + tig];
                const uint32_t* bn = reinterpret_cast<const uint32_t*>(&Bv);
#pragma unroll
                for (int ss = 0; ss < 2; ss++)
#pragma unroll
                    for (int mb = 0; mb < 2; mb++) {
                        const uint32_t* ag  = reinterpret_cast<const uint32_t*>(&Ag[mb]);
                        const uint32_t* ag8 = reinterpret_cast<const uint32_t*>(&Ag8[mb]);
                        mma16(yacc[mb][nt], ag[2*ss], ag8[2*ss], ag[2*ss+1], ag8[2*ss+1],
                              bn[2*ss], bn[2*ss+1]);
                    }
            }
        }
        __syncthreads();               // all ph2 reads of T[s] done

        // refill T[s] for iteration j+2; commit the (Xj,T) group
        if (j + 2 < NJT) { loadT((j + 2) * JT, ttOff[s]); CP_COMMIT(); }
    }

    // epilogue
    float* Yb = y + ((size_t)b * HW_DIM + i0) * C_DIM;
#pragma unroll
    for (int mb = 0; mb < 2; mb++) {
        int r1 = 32 * wr + 16 * mb + gid;
#pragma unroll
        for (int nt = 0; nt < 8; nt++) {
            int c = 64 * wn + 8 * nt + 2 * tig;
            *reinterpret_cast<float2*>(&Yb[(size_t)r1 * C_DIM + c]) =
                make_float2(yacc[mb][nt][0], yacc[mb][nt][1]);
            *reinterpret_cast<float2*>(&Yb[(size_t)(r1 + 8) * C_DIM + c]) =
                make_float2(yacc[mb][nt][2], yacc[mb][nt][3]);
        }
    }
}

// ---------------------------------------------------------------------------
extern "C" void kernel_launch(void* const* d_in, const int* in_sizes, int n_in,
                              void* d_out, int out_size) {
    const float* x = (const float*)d_in[0];
    const float* W = (const float*)d_in[1];
    float* y = (float*)d_out;
    (void)in_sizes; (void)n_in; (void)out_size;

    norm_kernel<<<NROWS / 8, dim3(32, 8)>>>(x);
    transform_kernel<<<dim3(NROWS / 64, C_DIM / 64), 256>>>(x, W);

    cudaFuncSetAttribute(ppm_fused, cudaFuncAttributeMaxDynamicSharedMemorySize, SM_TOT);
    ppm_fused<<<dim3(HW_DIM / JT, B_DIM), 256, SM_TOT>>>(y);
}

// round 11
// speedup vs baseline: 1.2649x; 1.2052x over previous
#include <cuda_runtime.h>
#include <cuda_fp16.h>
#include <math.h>
#include <stdint.h>

#define B_DIM   8
#define HW_DIM  3136
#define C_DIM   256
#define NROWS   (B_DIM * HW_DIM)        // 25088
#define JT      64                      // j tile
#define NJT     (HW_DIM / JT)           // 49

// fused smem (bytes). X rows pitch 36 u4, T/S rows pitch 12 u4 (=4 mod 8 ->
// conflict-free LDS.128 fragment gathers). Xj and T double-buffered.
#define XP      36
#define TP      12
#define SM_XI   0                       // 64*36*16  = 36864
#define SM_XJ0  36864
#define SM_XJ1  73728
#define SM_TT0  110592                  // 256*12*16 = 49152
#define SM_TT1  159744
#define SM_SS   208896                  // 64*12*16  = 12288
#define SM_TOT  221184

// transform_mma smem: Wt 256 rows x 36 u4, X/staging 64x36 u4 (36864 B)
#define TM_WT   0
#define TM_XT   147456
#define TM_TOT  184320

// device-global scratch (fp16)
__device__ __align__(16) unsigned short g_xn[(size_t)NROWS * C_DIM];          // xn [row][c]
__device__ __align__(16) unsigned short g_xh[(size_t)NROWS * C_DIM];          // raw x fp16
__device__ __align__(16) unsigned short g_wt[(size_t)C_DIM * C_DIM];          // W^T [c][k]
__device__ __align__(16) unsigned short g_tt[(size_t)B_DIM * C_DIM * HW_DIM]; // t  [b][c][hw]

__device__ __forceinline__ uint32_t h2pack(float a, float b) {
    __half2 h = __floats2half2_rn(a, b);
    return *reinterpret_cast<uint32_t*>(&h);
}
__device__ __forceinline__ uint32_t smem_u32(const void* p) {
    uint32_t a;
    asm("{ .reg .u64 t; cvta.to.shared.u64 t, %1; cvt.u32.u64 %0, t; }" : "=r"(a) : "l"(p));
    return a;
}
__device__ __forceinline__ void cp16(uint32_t dst, const void* src) {
    asm volatile("{ .reg .u64 g; cvta.to.global.u64 g, %1;"
                 " cp.async.cg.shared.global [%0], [g], 16; }" :: "r"(dst), "l"(src));
}
#define CP_COMMIT() asm volatile("cp.async.commit_group;" ::: "memory")
#define CP_WAIT0()  asm volatile("cp.async.wait_group 0;" ::: "memory")
#define CP_WAIT1()  asm volatile("cp.async.wait_group 1;" ::: "memory")

__device__ __forceinline__ void mma16(float* d, uint32_t a0, uint32_t a1,
                                      uint32_t a2, uint32_t a3,
                                      uint32_t b0, uint32_t b1) {
    asm volatile(
        "mma.sync.aligned.m16n8k16.row.col.f32.f16.f16.f32 "
        "{%0,%1,%2,%3}, {%4,%5,%6,%7}, {%8,%9}, {%0,%1,%2,%3};"
        : "+f"(d[0]), "+f"(d[1]), "+f"(d[2]), "+f"(d[3])
        : "r"(a0), "r"(a1), "r"(a2), "r"(a3), "r"(b0), "r"(b1));
}

// ---------------------------------------------------------------------------
// Kernel A: L2 normalize -> g_xn (fp16) and raw x -> g_xh (fp16)
// ---------------------------------------------------------------------------
__global__ void norm_kernel(const float* __restrict__ x) {
    int row  = blockIdx.x * 8 + threadIdx.y;
    int lane = threadIdx.x;
    const float4* xr = reinterpret_cast<const float4*>(x) + (size_t)row * (C_DIM / 4);
    float4 v0 = xr[lane];
    float4 v1 = xr[lane + 32];
    float s = v0.x*v0.x + v0.y*v0.y + v0.z*v0.z + v0.w*v0.w
            + v1.x*v1.x + v1.y*v1.y + v1.z*v1.z + v1.w*v1.w;
#pragma unroll
    for (int off = 16; off > 0; off >>= 1) s += __shfl_xor_sync(0xffffffffu, s, off);
    float inv = rsqrtf(fmaxf(s, 1e-12f));
    uint2* oh = reinterpret_cast<uint2*>(g_xh) + (size_t)row * (C_DIM / 4);
    oh[lane]      = make_uint2(h2pack(v0.x, v0.y), h2pack(v0.z, v0.w));
    oh[lane + 32] = make_uint2(h2pack(v1.x, v1.y), h2pack(v1.z, v1.w));
    uint2* o = reinterpret_cast<uint2*>(g_xn) + (size_t)row * (C_DIM / 4);
    o[lane]      = make_uint2(h2pack(v0.x*inv, v0.y*inv), h2pack(v0.z*inv, v0.w*inv));
    o[lane + 32] = make_uint2(h2pack(v1.x*inv, v1.y*inv), h2pack(v1.z*inv, v1.w*inv));
}

// ---------------------------------------------------------------------------
// Kernel A2: W^T -> g_wt[c][k] fp16 (tiny one-shot)
// ---------------------------------------------------------------------------
__global__ void wt_kernel(const float* __restrict__ W) {
    int c = blockIdx.x, k = threadIdx.x;
    g_wt[(size_t)c * C_DIM + k] = __half_as_ushort(__float2half_rn(W[(size_t)k * C_DIM + c]));
}

// ---------------------------------------------------------------------------
// Kernel B: t = x @ W on fp16 tensor cores; stored transposed: g_tt[b][c][hw].
//   CTA: 256 thr, 64 rows x 256 cols, K=256. W^T fully smem-resident.
//   Epilogue staged through smem (transpose) -> coalesced 16B stores.
// ---------------------------------------------------------------------------
__global__ __launch_bounds__(256)
void transform_mma() {
    extern __shared__ char smem[];
    uint32_t sbase = smem_u32(smem);
    const uint4* Wt4 = reinterpret_cast<const uint4*>(smem + TM_WT);
    const uint4* X4  = reinterpret_cast<const uint4*>(smem + TM_XT);
    __half*      stg = reinterpret_cast<__half*>(smem + TM_XT);   // reused after compute

    int row0 = blockIdx.x * 64;
    int tid = threadIdx.x, w = tid >> 5, lane = tid & 31;
    int gid = lane >> 2, tig = lane & 3;
    int wr = w & 1, wn = w >> 1;

    // load Wt (8192 u4) + X rows (2048 u4)
#pragma unroll
    for (int q = 0; q < 32; q++) {
        int idx = tid + q * 256, r = idx >> 5, c4 = idx & 31;
        cp16(sbase + TM_WT + (uint32_t)(r * XP + c4) * 16,
             g_wt + (size_t)r * C_DIM + c4 * 8);
    }
#pragma unroll
    for (int q = 0; q < 8; q++) {
        int idx = tid + q * 256, r = idx >> 5, c4 = idx & 31;
        cp16(sbase + TM_XT + (uint32_t)(r * XP + c4) * 16,
             g_xh + (size_t)(row0 + r) * C_DIM + c4 * 8);
    }
    CP_COMMIT(); CP_WAIT0();
    __syncthreads();

    float yacc[2][8][4];
#pragma unroll
    for (int mb = 0; mb < 2; mb++)
#pragma unroll
        for (int nt = 0; nt < 8; nt++)
#pragma unroll
            for (int q = 0; q < 4; q++) yacc[mb][nt][q] = 0.f;

    // warp tile 32x64, K=256
#pragma unroll
    for (int kc = 0; kc < 8; kc++) {
        uint4 Ag[2], Ag8[2];
#pragma unroll
        for (int mb = 0; mb < 2; mb++) {
            int r1 = 32 * wr + 16 * mb + gid;
            Ag[mb]  = X4[r1 * XP + 4 * kc + tig];
            Ag8[mb] = X4[(r1 + 8) * XP + 4 * kc + tig];
        }
#pragma unroll
        for (int nt = 0; nt < 8; nt++) {
            int c = 64 * wn + 8 * nt + gid;
            uint4 Bv = Wt4[c * XP + 4 * kc + tig];
            const uint32_t* bn = reinterpret_cast<const uint32_t*>(&Bv);
#pragma unroll
            for (int ss = 0; ss < 2; ss++)
#pragma unroll
                for (int mb = 0; mb < 2; mb++) {
                    const uint32_t* ag  = reinterpret_cast<const uint32_t*>(&Ag[mb]);
                    const uint32_t* ag8 = reinterpret_cast<const uint32_t*>(&Ag8[mb]);
                    mma16(yacc[mb][nt], ag[2*ss], ag8[2*ss], ag[2*ss+1], ag8[2*ss+1],
                          bn[2*ss], bn[2*ss+1]);
                }
        }
    }
    __syncthreads();           // X reads done; reuse buffer as staging [c][row]

    // stage transposed (pitch 72 halves per c-row)
#pragma unroll
    for (int mb = 0; mb < 2; mb++)
#pragma unroll
        for (int nt = 0; nt < 8; nt++) {
            int r1 = 32 * wr + 16 * mb + gid;
            int c  = 64 * wn + 8 * nt + 2 * tig;
            stg[c * 72 + r1]           = __float2half_rn(yacc[mb][nt][0]);
            stg[(c + 1) * 72 + r1]     = __float2half_rn(yacc[mb][nt][1]);
            stg[c * 72 + r1 + 8]       = __float2half_rn(yacc[mb][nt][2]);
            stg[(c + 1) * 72 + r1 + 8] = __float2half_rn(yacc[mb][nt][3]);
        }
    __syncthreads();

    // coalesced 16B stores along hw
    int bb = row0 / HW_DIM, hw0 = row0 - bb * HW_DIM;
#pragma unroll
    for (int p = 0; p < 4; p++) {
        int c = p * 64 + (tid >> 2), ch = tid & 3;
        uint4 v  = *reinterpret_cast<const uint4*>(&stg[c * 72 + ch * 16]);
        uint4 v2 = *reinterpret_cast<const uint4*>(&stg[c * 72 + ch * 16 + 8]);
        *reinterpret_cast<uint4*>(
            &g_tt[((size_t)bb * C_DIM + c) * HW_DIM + hw0 + ch * 16]) = v;
        *reinterpret_cast<uint4*>(
            &g_tt[((size_t)bb * C_DIM + c) * HW_DIM + hw0 + ch * 16 + 8]) = v2;
    }
}

// ---------------------------------------------------------------------------
// Kernel C: fused pass, mma.sync fp16, double-buffered pipeline (R9, 488-492us)
// ---------------------------------------------------------------------------
__global__ __launch_bounds__(256)
void ppm_fused(float* __restrict__ y) {
    extern __shared__ char smem[];
    uint32_t sbase = smem_u32(smem);
    const uint4* Xi4 = reinterpret_cast<const uint4*>(smem + SM_XI);
    uint32_t*    sS  = reinterpret_cast<uint32_t*>(smem + SM_SS);
    const uint4* S4  = reinterpret_cast<const uint4*>(smem + SM_SS);

    int b  = blockIdx.y;
    int i0 = blockIdx.x * JT;
    const unsigned short* Xg = g_xn + (size_t)b * HW_DIM * C_DIM;
    const unsigned short* Tg = g_tt + (size_t)b * C_DIM * HW_DIM;

    int tid = threadIdx.x, w = tid >> 5, lane = tid & 31;
    int gid = lane >> 2, tig = lane & 3;
    int wr = w & 1, wn = w >> 1;

    const uint32_t xjOff[2] = {SM_XJ0, SM_XJ1};
    const uint32_t ttOff[2] = {SM_TT0, SM_TT1};

    auto loadX = [&](int r0, uint32_t dstb) {
#pragma unroll
        for (int q = 0; q < 8; q++) {
            int idx = tid + q * 256, r = idx >> 5, c4 = idx & 31;
            cp16(sbase + dstb + (uint32_t)(r * XP + c4) * 16,
                 Xg + (size_t)(r0 + r) * C_DIM + c4 * 8);
        }
    };
    auto loadT = [&](int j0, uint32_t dstb) {
#pragma unroll
        for (int q = 0; q < 8; q++) {
            int idx = tid + q * 256, c = idx >> 3, k4 = idx & 7;
            cp16(sbase + dstb + (uint32_t)(c * TP + k4) * 16,
                 Tg + (size_t)c * HW_DIM + j0 + k4 * 8);
        }
    };

    loadX(i0, SM_XI);
    loadX(0, SM_XJ0);
    loadT(0, SM_TT0);
    CP_COMMIT();
    loadX(JT, SM_XJ1);
    loadT(JT, SM_TT1);
    CP_COMMIT();

    float yacc[2][8][4];
#pragma unroll
    for (int mb = 0; mb < 2; mb++)
#pragma unroll
        for (int nt = 0; nt < 8; nt++)
#pragma unroll
            for (int q = 0; q < 4; q++) yacc[mb][nt][q] = 0.f;

    for (int j = 0; j < NJT; j++) {
        int s = j & 1;
        if (j == NJT - 1) CP_WAIT0(); else CP_WAIT1();
        __syncthreads();
        const uint4* Xj4 = reinterpret_cast<const uint4*>(smem + xjOff[s]);
        const uint4* T4  = reinterpret_cast<const uint4*>(smem + ttOff[s]);

        // phase 1: S(32x16/warp) = Xi @ Xj^T over K=256
        float sacc[2][2][4] = {};
#pragma unroll
        for (int kc = 0; kc < 8; kc++) {
            uint4 Ag[2], Ag8[2];
#pragma unroll
            for (int mb = 0; mb < 2; mb++) {
                int r1 = 32 * wr + 16 * mb + gid;
                Ag[mb]  = Xi4[r1 * XP + 4 * kc + tig];
                Ag8[mb] = Xi4[(r1 + 8) * XP + 4 * kc + tig];
            }
            uint4 Bn[2];
#pragma unroll
            for (int nb = 0; nb < 2; nb++) {
                int n1 = 16 * wn + 8 * nb + gid;
                Bn[nb] = Xj4[n1 * XP + 4 * kc + tig];
            }
#pragma unroll
            for (int ss = 0; ss < 2; ss++)
#pragma unroll
                for (int mb = 0; mb < 2; mb++) {
                    const uint32_t* ag  = reinterpret_cast<const uint32_t*>(&Ag[mb]);
                    const uint32_t* ag8 = reinterpret_cast<const uint32_t*>(&Ag8[mb]);
#pragma unroll
                    for (int nb = 0; nb < 2; nb++) {
                        const uint32_t* bn = reinterpret_cast<const uint32_t*>(&Bn[nb]);
                        mma16(sacc[mb][nb], ag[2*ss], ag8[2*ss], ag[2*ss+1], ag8[2*ss+1],
                              bn[2*ss], bn[2*ss+1]);
                    }
                }
        }
        // relu^2 -> sS
#pragma unroll
        for (int mb = 0; mb < 2; mb++)
#pragma unroll
            for (int nb = 0; nb < 2; nb++) {
                int r1 = 32 * wr + 16 * mb + gid;
                int cw = 8 * wn + 4 * nb + tig;
                float v0 = fmaxf(sacc[mb][nb][0], 0.f), v1 = fmaxf(sacc[mb][nb][1], 0.f);
                float v2 = fmaxf(sacc[mb][nb][2], 0.f), v3 = fmaxf(sacc[mb][nb][3], 0.f);
                sS[r1 * (TP * 4) + cw]       = h2pack(v0 * v0, v1 * v1);
                sS[(r1 + 8) * (TP * 4) + cw] = h2pack(v2 * v2, v3 * v3);
            }
        __syncthreads();

        if (j + 2 < NJT) loadX((j + 2) * JT, xjOff[s]);

        // phase 2: Y(32x64/warp) += S @ T over K=64
#pragma unroll
        for (int kc = 0; kc < 2; kc++) {
            uint4 Ag[2], Ag8[2];
#pragma unroll
            for (int mb = 0; mb < 2; mb++) {
                int r1 = 32 * wr + 16 * mb + gid;
                Ag[mb]  = S4[r1 * TP + 4 * kc + tig];
                Ag8[mb] = S4[(r1 + 8) * TP + 4 * kc + tig];
            }
#pragma unroll
            for (int nt = 0; nt < 8; nt++) {
                int c = 64 * wn + 8 * nt + gid;
                uint4 Bv = T4[c * TP + 4 * kc + tig];
                const uint32_t* bn = reinterpret_cast<const uint32_t*>(&Bv);
#pragma unroll
                for (int ss = 0; ss < 2; ss++)
#pragma unroll
                    for (int mb = 0; mb < 2; mb++) {
                        const uint32_t* ag  = reinterpret_cast<const uint32_t*>(&Ag[mb]);
                        const uint32_t* ag8 = reinterpret_cast<const uint32_t*>(&Ag8[mb]);
                        mma16(yacc[mb][nt], ag[2*ss], ag8[2*ss], ag[2*ss+1], ag8[2*ss+1],
                              bn[2*ss], bn[2*ss+1]);
                    }
            }
        }
        __syncthreads();

        if (j + 2 < NJT) { loadT((j + 2) * JT, ttOff[s]); CP_COMMIT(); }
    }

    float* Yb = y + ((size_t)b * HW_DIM + i0) * C_DIM;
#pragma unroll
    for (int mb = 0; mb < 2; mb++) {
        int r1 = 32 * wr + 16 * mb + gid;
#pragma unroll
        for (int nt = 0; nt < 8; nt++) {
            int c = 64 * wn + 8 * nt + 2 * tig;
            *reinterpret_cast<float2*>(&Yb[(size_t)r1 * C_DIM + c]) =
                make_float2(yacc[mb][nt][0], yacc[mb][nt][1]);
            *reinterpret_cast<float2*>(&Yb[(size_t)(r1 + 8) * C_DIM + c]) =
                make_float2(yacc[mb][nt][2], yacc[mb][nt][3]);
        }
    }
}

// ---------------------------------------------------------------------------
extern "C" void kernel_launch(void* const* d_in, const int* in_sizes, int n_in,
                              void* d_out, int out_size) {
    const float* x = (const float*)d_in[0];
    const float* W = (const float*)d_in[1];
    float* y = (float*)d_out;
    (void)in_sizes; (void)n_in; (void)out_size;

    norm_kernel<<<NROWS / 8, dim3(32, 8)>>>(x);
    wt_kernel<<<C_DIM, C_DIM>>>(W);

    cudaFuncSetAttribute(transform_mma, cudaFuncAttributeMaxDynamicSharedMemorySize, TM_TOT);
    transform_mma<<<NROWS / 64, 256, TM_TOT>>>();

    cudaFuncSetAttribute(ppm_fused, cudaFuncAttributeMaxDynamicSharedMemorySize, SM_TOT);
    ppm_fused<<<dim3(HW_DIM / JT, B_DIM), 256, SM_TOT>>>(y);
}